// round 12
// baseline (speedup 1.0000x reference)
#include <cuda_runtime.h>
#include <cuda_bf16.h>
#include <stdint.h>
#include <math.h>

#define PADW 66
#define CH   144
#define NB   16
#define LT   12

static constexpr size_t PLANE = (size_t)NB * PADW * PADW * CH;   // bf16 elems per split plane

// ---- persistent scratch ----
__device__ __nv_bfloat16 g_act0[2][2 * PLANE];     // L0 input ping-pong: [hi|lo]
__device__ __nv_bfloat16 g_act1[2][2 * PLANE];     // L1 input ping-pong
__device__ float g_c0[(size_t)NB * 4096 * 128];
__device__ float g_c1[(size_t)NB * 4096 * 12];
__device__ uint32_t g_fb0[9 * 2 * 8 * 9 * 8 * 32 * 2];   // [kc][bsel][ntile][tap][nsub][lane][reg]
__device__ uint32_t g_fb1[9 * 2 * 1 * 9 * 8 * 32 * 2];

__global__ void fill16(uint4* __restrict__ p, size_t n) {
    size_t i = (size_t)blockIdx.x * blockDim.x + threadIdx.x;
    size_t st = (size_t)gridDim.x * blockDim.x;
    uint4 z = make_uint4(0, 0, 0, 0);
    for (; i < n; i += st) p[i] = z;
}

__device__ __forceinline__ float fsig(float x) { return 1.0f / (1.0f + __expf(-x)); }
__device__ __forceinline__ float ftanh(float x) {
    float e = __expf(2.0f * x);
    return 1.0f - 2.0f / (e + 1.0f);
}

__device__ __forceinline__ void cpa16(uint32_t dst, const void* src) {
    asm volatile("cp.async.cg.shared.global [%0], [%1], 16;" :: "r"(dst), "l"(src));
}

// Build per-lane B fragments, gate-interleaved (n' = 4*hid + gate), hi/lo split.
// Layout: [kc][bsel][ntile][tap][nsub][lane][reg] -> per-(kc,bsel,ntile) slice contiguous.
__global__ void prep_w(const float* __restrict__ W, uint32_t* __restrict__ dst,
                       int HIDT, int NTILES, int CIN, int mode0, int total) {
    int idx = blockIdx.x * blockDim.x + threadIdx.x;
    if (idx >= total) return;
    int r    = idx & 1;
    int lane = (idx >> 1) & 31;
    int nsub = (idx >> 6) & 7;
    int rest = idx >> 9;
    int tap  = rest % 9;  rest /= 9;
    int nt   = rest % NTILES; rest /= NTILES;
    int bsel = rest & 1;
    int kc   = rest >> 1;
    int n    = ((nt * 8 + nsub) << 3) + (lane >> 2);
    int hid  = n >> 2, gate = n & 3;
    int ch0  = kc * 16 + (lane & 3) * 2 + r * 8;
    uint32_t out = 0;
#pragma unroll
    for (int s = 0; s < 2; ++s) {
        int ch = ch0 + s;
        int cin = mode0 ? (ch == 128 ? 0 : (ch < 128 ? ch + 1 : -1))
                        : (ch < CIN ? ch : -1);
        float w = 0.f;
        if (cin >= 0 && hid < HIDT)
            w = W[((size_t)(gate * HIDT + hid) * CIN + cin) * 9 + tap];
        __nv_bfloat16 hi = __float2bfloat16(w);
        __nv_bfloat16 v = bsel ? __float2bfloat16(w - __bfloat162float(hi)) : hi;
        out |= (uint32_t)__bfloat16_as_ushort(v) << (s * 16);
    }
    dst[idx] = out;
}

// Inject x_t at channel 128 (hi/lo) of act0[t&1].
__global__ void inject_x(const float* __restrict__ hist, int t, __nv_bfloat16* __restrict__ act) {
    int idx = blockIdx.x * blockDim.x + threadIdx.x;
    if (idx >= NB * 4096) return;
    int b = idx >> 12, px = idx & 4095;
    float v = hist[((size_t)b * LT + t) * 4096 + px];
    size_t e = (((size_t)b * PADW + (px >> 6) + 1) * PADW + ((px & 63) + 1)) * CH + 128;
    __nv_bfloat16 hi = __float2bfloat16(v);
    act[e] = hi;
    act[PLANE + e] = __float2bfloat16(v - __bfloat162float(hi));
}

// ==================== fused ConvLSTM step: implicit GEMM on mma.sync bf16 ====================
// CTA: M=256 px (4 image rows), N=64 gate-interleaved oc'. 8 warps = 4(M) x 2(N), warp 64x32.
// 27 uniform phases (9 kc x {Ahi*Bhi, Ahi*Blo, Alo*Bhi}); 2-deep cp.async pipeline.
// smem: A hi slot [0,19008) + A lo slot [19008,38016); B 2 slots of 18432 at 38016.
__global__ void __launch_bounds__(256, 2)
step_mma(const __nv_bfloat16* __restrict__ act,      // hi plane; lo = act + PLANE
         const uint32_t* __restrict__ fragB, int ntiles,
         const float* __restrict__ bias, int HIDT,
         float* __restrict__ cstate,
         __nv_bfloat16* hdst_a, __nv_bfloat16* hdst_b, int ch_off,
         float* out_final) {
    extern __shared__ unsigned char smem[];
    uint32_t* sB = (uint32_t*)(smem + 38016);
    const uint32_t sAsh = (uint32_t)__cvta_generic_to_shared(smem);
    const uint32_t sBsh = sAsh + 38016;

    const int tid = threadIdx.x, lane = tid & 31, warp = tid >> 5;
    const int warpM = warp & 3, warpN = warp >> 2;
    const int R4 = blockIdx.x * 4;           // image-row base (also padded slab row base)
    const int b  = blockIdx.y;
    const int zt = blockIdx.z;
    const int nro = zt * 64;

    float acc[4][4][4];
#pragma unroll
    for (int m = 0; m < 4; ++m)
#pragma unroll
        for (int i = 0; i < 4; ++i)
#pragma unroll
            for (int k = 0; k < 4; ++k) acc[m][i][k] = 0.f;

    const size_t actbase = ((size_t)b * PADW + R4) * PADW * CH;

    // ---- loader for phase p (all threads participate; one cp.async group)
    auto issue = [&](int p) {
        const int kc = p / 3, sub = p - kc * 3;
        if (sub != 1) {      // A slab: 396 rows x 16 ch, row stride 48B
            const __nv_bfloat16* pl = act + (sub == 2 ? PLANE : 0);
            const uint32_t abuf = sAsh + (sub == 2 ? 19008u : 0u);
            for (int i = tid; i < 396 * 2; i += 256) {
                int rowid = i >> 1, half = i & 1;
                cpa16(abuf + rowid * 48 + half * 16,
                      pl + actbase + (size_t)rowid * CH + kc * 16 + half * 8);
            }
        }
        {                    // B slice (kc,bsel): 1152 uint4
            const int bsel = (sub == 1);
            const uint4* src = (const uint4*)fragB + (size_t)((kc * 2 + bsel) * ntiles + zt) * 1152;
            const uint32_t bbuf = sBsh + (p & 1) * 18432u;
            for (int i = tid; i < 1152; i += 256) cpa16(bbuf + i * 16, src + i);
        }
        asm volatile("cp.async.commit_group;" ::: "memory");
    };

    issue(0);
    issue(1);
    for (int p = 0; p < 27; ++p) {
        if (p < 26) asm volatile("cp.async.wait_group 1;" ::: "memory");
        else        asm volatile("cp.async.wait_group 0;" ::: "memory");
        __syncthreads();
        const uint32_t aBase = sAsh + ((p % 3) == 2 ? 19008u : 0u);
        const uint32_t* sBp = sB + (p & 1) * 4608;
#pragma unroll
        for (int tap = 0; tap < 9; ++tap) {
            const int ky = tap / 3, kx = tap % 3;
            uint32_t a[4][4];
#pragma unroll
            for (int msub = 0; msub < 4; ++msub) {
                int m = warpM * 64 + msub * 16 + (lane & 15);
                int srow = ((m >> 6) + ky) * 66 + (m & 63) + kx;
                uint32_t ad = aBase + srow * 48 + (lane >> 4) * 16;
                asm volatile("ldmatrix.sync.aligned.m8n8.x4.shared.b16 {%0,%1,%2,%3}, [%4];"
                    : "=r"(a[msub][0]), "=r"(a[msub][1]), "=r"(a[msub][2]), "=r"(a[msub][3])
                    : "r"(ad));
            }
#pragma unroll
            for (int i = 0; i < 4; ++i) {
                const uint32_t* bp = sBp + (((tap * 8) + warpN * 4 + i) * 32 + lane) * 2;
                uint32_t b0 = bp[0], b1 = bp[1];
#pragma unroll
                for (int msub = 0; msub < 4; ++msub) {
                    asm volatile(
                        "mma.sync.aligned.m16n8k16.row.col.f32.bf16.bf16.f32 "
                        "{%0,%1,%2,%3}, {%4,%5,%6,%7}, {%8,%9}, {%0,%1,%2,%3};"
                        : "+f"(acc[msub][i][0]), "+f"(acc[msub][i][1]),
                          "+f"(acc[msub][i][2]), "+f"(acc[msub][i][3])
                        : "r"(a[msub][0]), "r"(a[msub][1]), "r"(a[msub][2]), "r"(a[msub][3]),
                          "r"(b0), "r"(b1));
                }
            }
        }
        __syncthreads();                 // compute(p) done before overwriting its buffers
        if (p + 2 < 27) issue(p + 2);
    }

    // ---- epilogue: gather 4 gates per (px,hid) via shfl, LSTM update ----
    const int q = lane & 3;
    const bool evenq = !(q & 1);
#pragma unroll
    for (int msub = 0; msub < 4; ++msub) {
#pragma unroll
        for (int i = 0; i < 4; ++i) {
            float d0 = acc[msub][i][0], d1 = acc[msub][i][1];
            float d2 = acc[msub][i][2], d3 = acc[msub][i][3];
            float s0 = evenq ? d2 : d0;
            float s1 = evenq ? d3 : d1;
            float t0 = __shfl_xor_sync(0xffffffffu, s0, 1);
            float t1 = __shfl_xor_sync(0xffffffffu, s1, 1);
            float zi, zf, zo, zg;
            int pr;
            if (evenq) { zi = d0; zf = d1; zo = t0; zg = t1; pr = lane >> 2; }
            else       { zi = t0; zf = t1; zo = d2; zg = d3; pr = (lane >> 2) + 8; }
            const int m = warpM * 64 + msub * 16 + pr;
            const int hid = (nro >> 2) + warpN * 8 + i * 2 + (q >> 1);
            if (hid < HIDT) {
                zi += bias[hid];
                zf += bias[HIDT + hid];
                zo += bias[2 * HIDT + hid];
                zg += bias[3 * HIDT + hid];
                const int r_im = m >> 6, x = m & 63;
                const size_t cidx = ((size_t)b * 4096 + (R4 + r_im) * 64 + x) * HIDT + hid;
                float cp = cstate[cidx];
                float cn = fsig(zf) * cp + fsig(zi) * ftanh(zg);
                float hn = fsig(zo) * ftanh(cn);
                cstate[cidx] = cn;
                __nv_bfloat16 hi = __float2bfloat16(hn);
                __nv_bfloat16 lo = __float2bfloat16(hn - __bfloat162float(hi));
                const size_t e = (((size_t)b * PADW + R4 + r_im + 1) * PADW + x + 1) * CH + ch_off + hid;
                if (hdst_a) { hdst_a[e] = hi; hdst_a[PLANE + e] = lo; }
                if (hdst_b) { hdst_b[e] = hi; hdst_b[PLANE + e] = lo; }
                if (out_final)
                    out_final[((size_t)b * HIDT + hid) * 4096 + (R4 + r_im) * 64 + x] = hn;
            }
        }
    }
}

// ==================== host ====================
extern "C" void kernel_launch(void* const* d_in, const int* in_sizes, int n_in,
                              void* d_out, int out_size) {
    const float* hist = (const float*)d_in[0];
    const float* W0   = (const float*)d_in[2];
    const float* b0   = (const float*)d_in[3];
    const float* W1   = (const float*)d_in[4];
    const float* b1   = (const float*)d_in[5];
    float* out = (float*)d_out;

    __nv_bfloat16 *a0p, *a1p;
    float *c0p, *c1p;
    uint32_t *fb0, *fb1;
    cudaGetSymbolAddress((void**)&a0p, g_act0);
    cudaGetSymbolAddress((void**)&a1p, g_act1);
    cudaGetSymbolAddress((void**)&c0p, g_c0);
    cudaGetSymbolAddress((void**)&c1p, g_c1);
    cudaGetSymbolAddress((void**)&fb0, g_fb0);
    cudaGetSymbolAddress((void**)&fb1, g_fb1);

    const int SMEM = 38016 + 2 * 18432;   // 74880
    cudaFuncSetAttribute(step_mma, cudaFuncAttributeMaxDynamicSharedMemorySize, SMEM);

    // deterministic replay: zero state + activations
    fill16<<<2048, 256>>>((uint4*)a0p, 4 * PLANE / 8);
    fill16<<<2048, 256>>>((uint4*)a1p, 4 * PLANE / 8);
    fill16<<<2048, 256>>>((uint4*)c0p, (size_t)NB * 4096 * 128 / 4);
    fill16<<<512,  256>>>((uint4*)c1p, (size_t)NB * 4096 * 12 / 4);

    const int tot0 = 9 * 2 * 8 * 9 * 8 * 32 * 2;
    const int tot1 = 9 * 2 * 1 * 9 * 8 * 32 * 2;
    prep_w<<<(tot0 + 255) / 256, 256>>>(W0, fb0, 128, 8, 129, 1, tot0);
    prep_w<<<(tot1 + 255) / 256, 256>>>(W1, fb1, 12, 1, 140, 0, tot1);

    const size_t BUF = 2 * PLANE;
    for (int t = 0; t < LT; ++t) {
        __nv_bfloat16* act0_t = a0p + (size_t)(t & 1) * BUF;
        __nv_bfloat16* act0_n = a0p + (size_t)((t + 1) & 1) * BUF;
        __nv_bfloat16* act1_t = a1p + (size_t)(t & 1) * BUF;
        __nv_bfloat16* act1_n = a1p + (size_t)((t + 1) & 1) * BUF;

        inject_x<<<256, 256>>>(hist, t, act0_t);
        // L0: reads act0[t]; writes h0 -> act0[t+1] ch0..127 and act1[t] ch0..127
        step_mma<<<dim3(16, 16, 8), 256, SMEM>>>(
            act0_t, fb0, 8, b0, 128, c0p, act0_n, act1_t, 0, nullptr);
        // L1: reads act1[t]; writes h1 -> act1[t+1] ch128..139; last step -> out
        step_mma<<<dim3(16, 16, 1), 256, SMEM>>>(
            act1_t, fb1, 1, b1, 12, c1p,
            (t < LT - 1) ? act1_n : nullptr, nullptr, 128,
            (t == LT - 1) ? out : nullptr);
    }
}

// round 13
// speedup vs baseline: 1.3453x; 1.3453x over previous
#include <cuda_runtime.h>
#include <cuda_bf16.h>
#include <cuda_fp16.h>
#include <stdint.h>
#include <math.h>

#define PADW 66
#define CH   144
#define NB   16
#define LT   12

static constexpr size_t PLANE = (size_t)NB * PADW * PADW * CH;   // 16-bit elems per plane

// ---- persistent scratch ----
// act buffers: 2 ping-pong bufs x [fp16 plane | bf16 plane]
__device__ uint16_t g_act0[2][2 * PLANE];
__device__ uint16_t g_act1[2][2 * PLANE];
__device__ float g_c0[(size_t)NB * 4096 * 128];
__device__ float g_c1[(size_t)NB * 4096 * 12];
__device__ uint32_t g_fb0[9 * 8 * 9 * 2 * 8 * 32 * 2];   // [kc][ntile][tap][bsel][nsub][lane][reg]
__device__ uint32_t g_fb1[9 * 1 * 9 * 2 * 8 * 32 * 2];

__global__ void fill16(uint4* __restrict__ p, size_t n) {
    size_t i = (size_t)blockIdx.x * blockDim.x + threadIdx.x;
    size_t st = (size_t)gridDim.x * blockDim.x;
    uint4 z = make_uint4(0, 0, 0, 0);
    for (; i < n; i += st) p[i] = z;
}

__device__ __forceinline__ float fsig(float x) { return 1.0f / (1.0f + __expf(-x)); }
__device__ __forceinline__ float ftanh(float x) {
    float e = __expf(2.0f * x);
    return 1.0f - 2.0f / (e + 1.0f);
}
__device__ __forceinline__ uint16_t f16bits(float v) { return __half_as_ushort(__float2half(v)); }
__device__ __forceinline__ uint16_t b16bits(float v) { return __bfloat16_as_ushort(__float2bfloat16(v)); }

__device__ __forceinline__ void cpa16(uint32_t dst, const void* src) {
    asm volatile("cp.async.cg.shared.global [%0], [%1], 16;" :: "r"(dst), "l"(src));
}
__device__ __forceinline__ void cpa_commit_wait() {
    asm volatile("cp.async.commit_group;" ::: "memory");
    asm volatile("cp.async.wait_group 0;" ::: "memory");
}

// Build per-lane B fragments, gate-interleaved (n' = 4*hid + gate).
// bsel=0: fp16(w); bsel=1: bf16(w - fp16(w))  (bf16 exponent range avoids subnormal flush).
__global__ void prep_w(const float* __restrict__ W, uint32_t* __restrict__ dst,
                       int HIDT, int NTILES, int CIN, int mode0, int total) {
    int idx = blockIdx.x * blockDim.x + threadIdx.x;
    if (idx >= total) return;
    int r    = idx & 1;
    int lane = (idx >> 1) & 31;
    int nsub = (idx >> 6) & 7;
    int bsel = (idx >> 9) & 1;
    int rest = idx >> 10;
    int tap  = rest % 9;  rest /= 9;
    int nt   = rest % NTILES;
    int kc   = rest / NTILES;
    int n    = ((nt * 8 + nsub) << 3) + (lane >> 2);
    int hid  = n >> 2, gate = n & 3;
    int ch0  = kc * 16 + (lane & 3) * 2 + r * 8;
    uint32_t out = 0;
#pragma unroll
    for (int s = 0; s < 2; ++s) {
        int ch = ch0 + s;
        int cin = mode0 ? (ch == 128 ? 0 : (ch < 128 ? ch + 1 : -1))
                        : (ch < CIN ? ch : -1);
        float w = 0.f;
        if (cin >= 0 && hid < HIDT)
            w = W[((size_t)(gate * HIDT + hid) * CIN + cin) * 9 + tap];
        uint16_t v;
        if (bsel == 0) v = f16bits(w);
        else           v = b16bits(w - __half2float(__float2half(w)));
        out |= (uint32_t)v << (s * 16);
    }
    dst[idx] = out;
}

// Inject x_t at channel 128 of act0[t&1]: fp16 plane + bf16 plane.
__global__ void inject_x(const float* __restrict__ hist, int t, uint16_t* __restrict__ act) {
    int idx = blockIdx.x * blockDim.x + threadIdx.x;
    if (idx >= NB * 4096) return;
    int b = idx >> 12, px = idx & 4095;
    float v = hist[((size_t)b * LT + t) * 4096 + px];
    size_t e = (((size_t)b * PADW + (px >> 6) + 1) * PADW + ((px & 63) + 1)) * CH + 128;
    act[e] = f16bits(v);
    act[PLANE + e] = b16bits(v);
}

// ==================== fused ConvLSTM step: implicit GEMM on mma.sync ====================
// CTA: M=256 px (4 image rows), N=64 gate-interleaved oc'. 8 warps = 4(M) x 2(N), warp 64x32.
// Per kc: load A slabs (fp16 + bf16 planes) + B block; 9 taps x {f16 main product, bf16 correction}.
__global__ void __launch_bounds__(256, 2)
step_mma(const uint16_t* __restrict__ act,      // fp16 plane; bf16 plane = act + PLANE
         const uint32_t* __restrict__ fragB, int ntiles,
         const float* __restrict__ bias, int HIDT,
         float* __restrict__ cstate,
         uint16_t* hdst_a, uint16_t* hdst_b, int ch_off,
         float* out_final) {
    extern __shared__ unsigned char smem[];
    uint32_t* sB = (uint32_t*)(smem + 38016);
    const uint32_t sAsh = (uint32_t)__cvta_generic_to_shared(smem);
    const uint32_t sBsh = sAsh + 38016;

    const int tid = threadIdx.x, lane = tid & 31, warp = tid >> 5;
    const int warpM = warp & 3, warpN = warp >> 2;
    const int R4 = blockIdx.x * 4;           // image-row base (also padded slab row base)
    const int b  = blockIdx.y;
    const int zt = blockIdx.z;
    const int nro = zt * 64;

    float acc[4][4][4];
#pragma unroll
    for (int m = 0; m < 4; ++m)
#pragma unroll
        for (int i = 0; i < 4; ++i)
#pragma unroll
            for (int k = 0; k < 4; ++k) acc[m][i][k] = 0.f;

    const size_t actbase = ((size_t)b * PADW + R4) * PADW * CH;

    for (int kc = 0; kc < 9; ++kc) {
        __syncthreads();    // previous phase compute done before overwriting smem
        // A slabs: 396 rows x 16 ch, row stride 48B, both planes (fp16 at 0, bf16 at 19008)
#pragma unroll
        for (int pl = 0; pl < 2; ++pl) {
            const uint16_t* src = act + (size_t)pl * PLANE;
            const uint32_t abuf = sAsh + pl * 19008u;
            for (int i = tid; i < 396 * 2; i += 256) {
                int rowid = i >> 1, half = i & 1;
                cpa16(abuf + rowid * 48 + half * 16,
                      src + actbase + (size_t)rowid * CH + kc * 16 + half * 8);
            }
        }
        // B block for this (kc, ztile): [tap][bsel][nsub][lane][reg]
        {
            const uint4* src = (const uint4*)fragB + (size_t)(kc * ntiles + zt) * 2304;
            for (int i = tid; i < 2304; i += 256) cpa16(sBsh + i * 16, src + i);
        }
        cpa_commit_wait();
        __syncthreads();
#pragma unroll
        for (int tap = 0; tap < 9; ++tap) {
            const int ky = tap / 3, kx = tap % 3;
#pragma unroll
            for (int bsel = 0; bsel < 2; ++bsel) {
                const uint32_t aBase = sAsh + bsel * 19008u;
                uint32_t a[4][4];
#pragma unroll
                for (int msub = 0; msub < 4; ++msub) {
                    int m = warpM * 64 + msub * 16 + (lane & 15);
                    int srow = ((m >> 6) + ky) * 66 + (m & 63) + kx;
                    uint32_t ad = aBase + srow * 48 + (lane >> 4) * 16;
                    asm volatile("ldmatrix.sync.aligned.m8n8.x4.shared.b16 {%0,%1,%2,%3}, [%4];"
                        : "=r"(a[msub][0]), "=r"(a[msub][1]), "=r"(a[msub][2]), "=r"(a[msub][3])
                        : "r"(ad));
                }
#pragma unroll
                for (int i = 0; i < 4; ++i) {
                    const uint32_t* bp = sB + ((((tap * 2 + bsel) * 8) + warpN * 4 + i) * 32 + lane) * 2;
                    uint32_t b0 = bp[0], b1 = bp[1];
#pragma unroll
                    for (int msub = 0; msub < 4; ++msub) {
                        if (bsel == 0) {
                            asm volatile(
                                "mma.sync.aligned.m16n8k16.row.col.f32.f16.f16.f32 "
                                "{%0,%1,%2,%3}, {%4,%5,%6,%7}, {%8,%9}, {%0,%1,%2,%3};"
                                : "+f"(acc[msub][i][0]), "+f"(acc[msub][i][1]),
                                  "+f"(acc[msub][i][2]), "+f"(acc[msub][i][3])
                                : "r"(a[msub][0]), "r"(a[msub][1]), "r"(a[msub][2]), "r"(a[msub][3]),
                                  "r"(b0), "r"(b1));
                        } else {
                            asm volatile(
                                "mma.sync.aligned.m16n8k16.row.col.f32.bf16.bf16.f32 "
                                "{%0,%1,%2,%3}, {%4,%5,%6,%7}, {%8,%9}, {%0,%1,%2,%3};"
                                : "+f"(acc[msub][i][0]), "+f"(acc[msub][i][1]),
                                  "+f"(acc[msub][i][2]), "+f"(acc[msub][i][3])
                                : "r"(a[msub][0]), "r"(a[msub][1]), "r"(a[msub][2]), "r"(a[msub][3]),
                                  "r"(b0), "r"(b1));
                        }
                    }
                }
            }
        }
    }

    // ---- epilogue: gather 4 gates per (px,hid) via shfl, LSTM update ----
    const int q = lane & 3;
    const bool evenq = !(q & 1);
#pragma unroll
    for (int msub = 0; msub < 4; ++msub) {
#pragma unroll
        for (int i = 0; i < 4; ++i) {
            float d0 = acc[msub][i][0], d1 = acc[msub][i][1];
            float d2 = acc[msub][i][2], d3 = acc[msub][i][3];
            float s0 = evenq ? d2 : d0;
            float s1 = evenq ? d3 : d1;
            float t0 = __shfl_xor_sync(0xffffffffu, s0, 1);
            float t1 = __shfl_xor_sync(0xffffffffu, s1, 1);
            float zi, zf, zo, zg;
            int pr;
            if (evenq) { zi = d0; zf = d1; zo = t0; zg = t1; pr = lane >> 2; }
            else       { zi = t0; zf = t1; zo = d2; zg = d3; pr = (lane >> 2) + 8; }
            const int m = warpM * 64 + msub * 16 + pr;
            const int hid = (nro >> 2) + warpN * 8 + i * 2 + (q >> 1);
            if (hid < HIDT) {
                zi += bias[hid];
                zf += bias[HIDT + hid];
                zo += bias[2 * HIDT + hid];
                zg += bias[3 * HIDT + hid];
                const int r_im = m >> 6, x = m & 63;
                const size_t cidx = ((size_t)b * 4096 + (R4 + r_im) * 64 + x) * HIDT + hid;
                float cp = cstate[cidx];
                float cn = fsig(zf) * cp + fsig(zi) * ftanh(zg);
                float hn = fsig(zo) * ftanh(cn);
                cstate[cidx] = cn;
                const uint16_t hf = f16bits(hn);
                const uint16_t hb = b16bits(hn);
                const size_t e = (((size_t)b * PADW + R4 + r_im + 1) * PADW + x + 1) * CH + ch_off + hid;
                if (hdst_a) { hdst_a[e] = hf; hdst_a[PLANE + e] = hb; }
                if (hdst_b) { hdst_b[e] = hf; hdst_b[PLANE + e] = hb; }
                if (out_final)
                    out_final[((size_t)b * HIDT + hid) * 4096 + (R4 + r_im) * 64 + x] = hn;
            }
        }
    }
}

// ==================== host ====================
extern "C" void kernel_launch(void* const* d_in, const int* in_sizes, int n_in,
                              void* d_out, int out_size) {
    const float* hist = (const float*)d_in[0];
    const float* W0   = (const float*)d_in[2];
    const float* b0   = (const float*)d_in[3];
    const float* W1   = (const float*)d_in[4];
    const float* b1   = (const float*)d_in[5];
    float* out = (float*)d_out;

    uint16_t *a0p, *a1p;
    float *c0p, *c1p;
    uint32_t *fb0, *fb1;
    cudaGetSymbolAddress((void**)&a0p, g_act0);
    cudaGetSymbolAddress((void**)&a1p, g_act1);
    cudaGetSymbolAddress((void**)&c0p, g_c0);
    cudaGetSymbolAddress((void**)&c1p, g_c1);
    cudaGetSymbolAddress((void**)&fb0, g_fb0);
    cudaGetSymbolAddress((void**)&fb1, g_fb1);

    const int SMEM = 38016 + 36864;   // 74880
    cudaFuncSetAttribute(step_mma, cudaFuncAttributeMaxDynamicSharedMemorySize, SMEM);

    // deterministic replay: zero state + activations (2 bufs x 2 planes x PLANE x 2B)
    fill16<<<2048, 256>>>((uint4*)a0p, 4 * PLANE * 2 / 16);
    fill16<<<2048, 256>>>((uint4*)a1p, 4 * PLANE * 2 / 16);
    fill16<<<2048, 256>>>((uint4*)c0p, (size_t)NB * 4096 * 128 / 4);
    fill16<<<512,  256>>>((uint4*)c1p, (size_t)NB * 4096 * 12 / 4);

    const int tot0 = 9 * 8 * 9 * 2 * 8 * 32 * 2;
    const int tot1 = 9 * 1 * 9 * 2 * 8 * 32 * 2;
    prep_w<<<(tot0 + 255) / 256, 256>>>(W0, fb0, 128, 8, 129, 1, tot0);
    prep_w<<<(tot1 + 255) / 256, 256>>>(W1, fb1, 12, 1, 140, 0, tot1);

    const size_t BUF = 2 * PLANE;
    for (int t = 0; t < LT; ++t) {
        uint16_t* act0_t = a0p + (size_t)(t & 1) * BUF;
        uint16_t* act0_n = a0p + (size_t)((t + 1) & 1) * BUF;
        uint16_t* act1_t = a1p + (size_t)(t & 1) * BUF;
        uint16_t* act1_n = a1p + (size_t)((t + 1) & 1) * BUF;

        inject_x<<<256, 256>>>(hist, t, act0_t);
        // L0: reads act0[t]; writes h0 -> act0[t+1] ch0..127 and act1[t] ch0..127
        step_mma<<<dim3(16, 16, 8), 256, SMEM>>>(
            act0_t, fb0, 8, b0, 128, c0p, act0_n, act1_t, 0, nullptr);
        // L1: reads act1[t]; writes h1 -> act1[t+1] ch128..139; last step -> out
        step_mma<<<dim3(16, 16, 1), 256, SMEM>>>(
            act1_t, fb1, 1, b1, 12, c1p,
            (t < LT - 1) ? act1_n : nullptr, nullptr, 128,
            (t == LT - 1) ? out : nullptr);
    }
}

// round 14
// speedup vs baseline: 2.2908x; 1.7028x over previous
#include <cuda_runtime.h>
#include <cuda_fp16.h>
#include <stdint.h>
#include <math.h>

#define PADW 66
#define CH   144
#define NB   16
#define LT   12

static constexpr size_t PLANE = (size_t)NB * PADW * PADW * CH;   // fp16 elems per plane

// ---- persistent scratch ----
__device__ uint16_t g_act0[2][PLANE];     // L0 input ping-pong (fp16)
__device__ uint16_t g_act1[2][PLANE];     // L1 input ping-pong
__device__ float g_c0[(size_t)NB * 4096 * 128];
__device__ float g_c1[(size_t)NB * 4096 * 12];
__device__ uint32_t g_fb0[9 * 8 * 9 * 2 * 32 * 8];   // [kc][ntile][tap][warpN][lane][slot8]
__device__ uint32_t g_fb1[9 * 1 * 9 * 2 * 32 * 8];

__global__ void fill16(uint4* __restrict__ p, size_t n) {
    size_t i = (size_t)blockIdx.x * blockDim.x + threadIdx.x;
    size_t st = (size_t)gridDim.x * blockDim.x;
    uint4 z = make_uint4(0, 0, 0, 0);
    for (; i < n; i += st) p[i] = z;
}

__device__ __forceinline__ float fsig(float x) { return 1.0f / (1.0f + __expf(-x)); }
__device__ __forceinline__ float ftanh(float x) {
    float e = __expf(2.0f * x);
    return 1.0f - 2.0f / (e + 1.0f);
}
__device__ __forceinline__ uint16_t f16bits(float v) { return __half_as_ushort(__float2half(v)); }

__device__ __forceinline__ void cpa16(uint32_t dst, const void* src) {
    asm volatile("cp.async.cg.shared.global [%0], [%1], 16;" :: "r"(dst), "l"(src));
}
__device__ __forceinline__ void cpa_commit_wait() {
    asm volatile("cp.async.commit_group;" ::: "memory");
    asm volatile("cp.async.wait_group 0;" ::: "memory");
}

// Build per-lane B fragments (fp16), gate-interleaved (n' = 4*hid + gate).
// Per (kc,ntile): [tap][warpN][lane][8 u32], the 8 u32 = [i][r] with the two 16B
// halves (i01 vs i23) swapped for lanes with (lane>>2)&1 == 1 (bank-conflict-free LDS.128).
__global__ void prep_w(const float* __restrict__ W, uint32_t* __restrict__ dst,
                       int HIDT, int NTILES, int CIN, int mode0, int total) {
    int idx = blockIdx.x * blockDim.x + threadIdx.x;
    if (idx >= total) return;
    int r8   = idx & 7;           // physical u32 slot in lane's 32B
    int lane = (idx >> 3) & 31;
    int wn   = (idx >> 8) & 1;
    int rest = idx >> 9;
    int tap  = rest % 9;  rest /= 9;
    int nt   = rest % NTILES;
    int kc   = rest / NTILES;
    int p    = r8 >> 2;           // physical 16B half
    int q2   = r8 & 3;
    int h    = p ^ ((lane >> 2) & 1);   // logical half
    int i    = h * 2 + (q2 >> 1);
    int r    = q2 & 1;
    int n    = (nt * 8 + wn * 4 + i) * 8 + (lane >> 2);
    int hid  = n >> 2, gate = n & 3;
    int ch0  = kc * 16 + (lane & 3) * 2 + r * 8;
    uint32_t out = 0;
#pragma unroll
    for (int s = 0; s < 2; ++s) {
        int ch = ch0 + s;
        int cin = mode0 ? (ch == 128 ? 0 : (ch < 128 ? ch + 1 : -1))
                        : (ch < CIN ? ch : -1);
        float w = 0.f;
        if (cin >= 0 && hid < HIDT)
            w = W[((size_t)(gate * HIDT + hid) * CIN + cin) * 9 + tap];
        out |= (uint32_t)f16bits(w) << (s * 16);
    }
    dst[idx] = out;
}

// Inject x_t at channel 128 of act0[t&1].
__global__ void inject_x(const float* __restrict__ hist, int t, uint16_t* __restrict__ act) {
    int idx = blockIdx.x * blockDim.x + threadIdx.x;
    if (idx >= NB * 4096) return;
    int b = idx >> 12, px = idx & 4095;
    float v = hist[((size_t)b * LT + t) * 4096 + px];
    size_t e = (((size_t)b * PADW + (px >> 6) + 1) * PADW + ((px & 63) + 1)) * CH + 128;
    act[e] = f16bits(v);
}

// ==================== fused ConvLSTM step: implicit GEMM on mma.sync fp16 ====================
// CTA: M=256 px (4 image rows), N=64 gate-interleaved oc'. 8 warps = 4(M) x 2(N), warp 64x32.
// 9 kc phases; per tap: 4 ldmatrix.x4 (A) + 2 LDS.128 (B) + 16 HMMA.
__global__ void __launch_bounds__(256, 2)
step_mma(const uint16_t* __restrict__ act,
         const uint32_t* __restrict__ fragB, int ntiles,
         const float* __restrict__ bias, int HIDT,
         float* __restrict__ cstate,
         uint16_t* hdst_a, uint16_t* hdst_b, int ch_off,
         float* out_final) {
    extern __shared__ unsigned char smem[];
    unsigned char* smB = smem + 19008;
    const uint32_t sAsh = (uint32_t)__cvta_generic_to_shared(smem);
    const uint32_t sBsh = sAsh + 19008;

    const int tid = threadIdx.x, lane = tid & 31, warp = tid >> 5;
    const int warpM = warp & 3, warpN = warp >> 2;
    const int R4 = blockIdx.x * 4;           // image-row base
    const int b  = blockIdx.y;
    const int zt = blockIdx.z;
    const int nro = zt * 64;

    const int sw = (lane >> 2) & 1;
    const uint32_t laneOff0 = (uint32_t)lane * 32 + sw * 16;        // logical half 0 (i=0,1)
    const uint32_t laneOff1 = (uint32_t)lane * 32 + (1 - sw) * 16;  // logical half 1 (i=2,3)

    float acc[4][4][4];
#pragma unroll
    for (int m = 0; m < 4; ++m)
#pragma unroll
        for (int i = 0; i < 4; ++i)
#pragma unroll
            for (int k = 0; k < 4; ++k) acc[m][i][k] = 0.f;

    const size_t actbase = ((size_t)b * PADW + R4) * PADW * CH;

    for (int kc = 0; kc < 9; ++kc) {
        __syncthreads();    // previous phase compute done before overwriting smem
        // A slab: 396 rows x 16 ch, row stride 48B
        for (int i = tid; i < 396 * 2; i += 256) {
            int rowid = i >> 1, half = i & 1;
            cpa16(sAsh + rowid * 48 + half * 16,
                  act + actbase + (size_t)rowid * CH + kc * 16 + half * 8);
        }
        // B block for this (kc, ztile): 1152 uint4
        {
            const uint4* src = (const uint4*)fragB + (size_t)(kc * ntiles + zt) * 1152;
            for (int i = tid; i < 1152; i += 256) cpa16(sBsh + i * 16, src + i);
        }
        cpa_commit_wait();
        __syncthreads();
#pragma unroll
        for (int tap = 0; tap < 9; ++tap) {
            const int ky = tap / 3, kx = tap % 3;
            uint32_t a[4][4];
#pragma unroll
            for (int msub = 0; msub < 4; ++msub) {
                int m = warpM * 64 + msub * 16 + (lane & 15);
                int srow = ((m >> 6) + ky) * 66 + (m & 63) + kx;
                uint32_t ad = sAsh + srow * 48 + (lane >> 4) * 16;
                asm volatile("ldmatrix.sync.aligned.m8n8.x4.shared.b16 {%0,%1,%2,%3}, [%4];"
                    : "=r"(a[msub][0]), "=r"(a[msub][1]), "=r"(a[msub][2]), "=r"(a[msub][3])
                    : "r"(ad));
            }
            const unsigned char* bblk = smB + (tap * 2 + warpN) * 1024;
            const uint4 vh0 = *(const uint4*)(bblk + laneOff0);   // i=0: x,y  i=1: z,w
            const uint4 vh1 = *(const uint4*)(bblk + laneOff1);   // i=2: x,y  i=3: z,w
            uint32_t bb[4][2] = {{vh0.x, vh0.y}, {vh0.z, vh0.w}, {vh1.x, vh1.y}, {vh1.z, vh1.w}};
#pragma unroll
            for (int i = 0; i < 4; ++i) {
#pragma unroll
                for (int msub = 0; msub < 4; ++msub) {
                    asm volatile(
                        "mma.sync.aligned.m16n8k16.row.col.f32.f16.f16.f32 "
                        "{%0,%1,%2,%3}, {%4,%5,%6,%7}, {%8,%9}, {%0,%1,%2,%3};"
                        : "+f"(acc[msub][i][0]), "+f"(acc[msub][i][1]),
                          "+f"(acc[msub][i][2]), "+f"(acc[msub][i][3])
                        : "r"(a[msub][0]), "r"(a[msub][1]), "r"(a[msub][2]), "r"(a[msub][3]),
                          "r"(bb[i][0]), "r"(bb[i][1]));
                }
            }
        }
    }

    // ---- epilogue: gather 4 gates per (px,hid) via shfl, LSTM update ----
    const int q = lane & 3;
    const bool evenq = !(q & 1);
#pragma unroll
    for (int msub = 0; msub < 4; ++msub) {
#pragma unroll
        for (int i = 0; i < 4; ++i) {
            float d0 = acc[msub][i][0], d1 = acc[msub][i][1];
            float d2 = acc[msub][i][2], d3 = acc[msub][i][3];
            float s0 = evenq ? d2 : d0;
            float s1 = evenq ? d3 : d1;
            float t0 = __shfl_xor_sync(0xffffffffu, s0, 1);
            float t1 = __shfl_xor_sync(0xffffffffu, s1, 1);
            float zi, zf, zo, zg;
            int pr;
            if (evenq) { zi = d0; zf = d1; zo = t0; zg = t1; pr = lane >> 2; }
            else       { zi = t0; zf = t1; zo = d2; zg = d3; pr = (lane >> 2) + 8; }
            const int m = warpM * 64 + msub * 16 + pr;
            const int hid = (nro >> 2) + warpN * 8 + i * 2 + (q >> 1);
            if (hid < HIDT) {
                zi += bias[hid];
                zf += bias[HIDT + hid];
                zo += bias[2 * HIDT + hid];
                zg += bias[3 * HIDT + hid];
                const int r_im = m >> 6, x = m & 63;
                const size_t cidx = ((size_t)b * 4096 + (R4 + r_im) * 64 + x) * HIDT + hid;
                float cp = cstate[cidx];
                float cn = fsig(zf) * cp + fsig(zi) * ftanh(zg);
                float hn = fsig(zo) * ftanh(cn);
                cstate[cidx] = cn;
                const uint16_t hf = f16bits(hn);
                const size_t e = (((size_t)b * PADW + R4 + r_im + 1) * PADW + x + 1) * CH + ch_off + hid;
                if (hdst_a) hdst_a[e] = hf;
                if (hdst_b) hdst_b[e] = hf;
                if (out_final)
                    out_final[((size_t)b * HIDT + hid) * 4096 + (R4 + r_im) * 64 + x] = hn;
            }
        }
    }
}

// ==================== host ====================
extern "C" void kernel_launch(void* const* d_in, const int* in_sizes, int n_in,
                              void* d_out, int out_size) {
    const float* hist = (const float*)d_in[0];
    const float* W0   = (const float*)d_in[2];
    const float* b0   = (const float*)d_in[3];
    const float* W1   = (const float*)d_in[4];
    const float* b1   = (const float*)d_in[5];
    float* out = (float*)d_out;

    uint16_t *a0p, *a1p;
    float *c0p, *c1p;
    uint32_t *fb0, *fb1;
    cudaGetSymbolAddress((void**)&a0p, g_act0);
    cudaGetSymbolAddress((void**)&a1p, g_act1);
    cudaGetSymbolAddress((void**)&c0p, g_c0);
    cudaGetSymbolAddress((void**)&c1p, g_c1);
    cudaGetSymbolAddress((void**)&fb0, g_fb0);
    cudaGetSymbolAddress((void**)&fb1, g_fb1);

    const int SMEM = 19008 + 18432;   // 37440
    cudaFuncSetAttribute(step_mma, cudaFuncAttributeMaxDynamicSharedMemorySize, SMEM);

    // deterministic replay: zero state + activations (2 bufs x PLANE x 2B each array)
    fill16<<<2048, 256>>>((uint4*)a0p, 2 * PLANE * 2 / 16);
    fill16<<<2048, 256>>>((uint4*)a1p, 2 * PLANE * 2 / 16);
    fill16<<<2048, 256>>>((uint4*)c0p, (size_t)NB * 4096 * 128 / 4);
    fill16<<<512,  256>>>((uint4*)c1p, (size_t)NB * 4096 * 12 / 4);

    const int tot0 = 9 * 8 * 9 * 2 * 32 * 8;
    const int tot1 = 9 * 1 * 9 * 2 * 32 * 8;
    prep_w<<<(tot0 + 255) / 256, 256>>>(W0, fb0, 128, 8, 129, 1, tot0);
    prep_w<<<(tot1 + 255) / 256, 256>>>(W1, fb1, 12, 1, 140, 0, tot1);

    for (int t = 0; t < LT; ++t) {
        uint16_t* act0_t = a0p + (size_t)(t & 1) * PLANE;
        uint16_t* act0_n = a0p + (size_t)((t + 1) & 1) * PLANE;
        uint16_t* act1_t = a1p + (size_t)(t & 1) * PLANE;
        uint16_t* act1_n = a1p + (size_t)((t + 1) & 1) * PLANE;

        inject_x<<<256, 256>>>(hist, t, act0_t);
        // L0: reads act0[t]; writes h0 -> act0[t+1] ch0..127 and act1[t] ch0..127
        step_mma<<<dim3(16, 16, 8), 256, SMEM>>>(
            act0_t, fb0, 8, b0, 128, c0p, act0_n, act1_t, 0, nullptr);
        // L1: reads act1[t]; writes h1 -> act1[t+1] ch128..139; last step -> out
        step_mma<<<dim3(16, 16, 1), 256, SMEM>>>(
            act1_t, fb1, 1, b1, 12, c1p,
            (t < LT - 1) ? act1_n : nullptr, nullptr, 128,
            (t == LT - 1) ? out : nullptr);
    }
}

// round 15
// speedup vs baseline: 2.4360x; 1.0634x over previous
#include <cuda_runtime.h>
#include <cuda_fp16.h>
#include <stdint.h>
#include <math.h>

#define PADW 66
#define CH   144
#define NB   16
#define LT   12

static constexpr size_t PLANE = (size_t)NB * PADW * PADW * CH;   // fp16 elems per plane

// ---- persistent scratch ----
__device__ uint16_t g_act0[2][PLANE];     // L0 input ping-pong (fp16)
__device__ uint16_t g_act1[2][PLANE];     // L1 input ping-pong
__device__ float g_c0[(size_t)NB * 4096 * 128];
__device__ float g_c1[(size_t)NB * 4096 * 12];
__device__ uint32_t g_fb0[9 * 8 * 9 * 2 * 32 * 8];   // [kc][ntile][tap][warpN][lane][slot8]
__device__ uint32_t g_fb1[9 * 1 * 9 * 2 * 32 * 8];

__global__ void fill16(uint4* __restrict__ p, size_t n) {
    size_t i = (size_t)blockIdx.x * blockDim.x + threadIdx.x;
    size_t st = (size_t)gridDim.x * blockDim.x;
    uint4 z = make_uint4(0, 0, 0, 0);
    for (; i < n; i += st) p[i] = z;
}

__device__ __forceinline__ float fsig(float x) { return 1.0f / (1.0f + __expf(-x)); }
__device__ __forceinline__ float ftanh(float x) {
    float e = __expf(2.0f * x);
    return 1.0f - 2.0f / (e + 1.0f);
}
__device__ __forceinline__ uint16_t f16bits(float v) { return __half_as_ushort(__float2half(v)); }

__device__ __forceinline__ void cpa16(uint32_t dst, const void* src) {
    asm volatile("cp.async.cg.shared.global [%0], [%1], 16;" :: "r"(dst), "l"(src));
}

// Build per-lane B fragments (fp16), gate-interleaved (n' = 4*hid + gate).
// Per (kc,ntile): [tap][warpN][lane][8 u32], the 8 u32 = [i][r] with the two 16B
// halves (i01 vs i23) swapped for lanes with (lane>>2)&1 == 1 (bank-conflict-free LDS.128).
__global__ void prep_w(const float* __restrict__ W, uint32_t* __restrict__ dst,
                       int HIDT, int NTILES, int CIN, int mode0, int total) {
    int idx = blockIdx.x * blockDim.x + threadIdx.x;
    if (idx >= total) return;
    int r8   = idx & 7;           // physical u32 slot in lane's 32B
    int lane = (idx >> 3) & 31;
    int wn   = (idx >> 8) & 1;
    int rest = idx >> 9;
    int tap  = rest % 9;  rest /= 9;
    int nt   = rest % NTILES;
    int kc   = rest / NTILES;
    int p    = r8 >> 2;           // physical 16B half
    int q2   = r8 & 3;
    int h    = p ^ ((lane >> 2) & 1);   // logical half
    int i    = h * 2 + (q2 >> 1);
    int r    = q2 & 1;
    int n    = (nt * 8 + wn * 4 + i) * 8 + (lane >> 2);
    int hid  = n >> 2, gate = n & 3;
    int ch0  = kc * 16 + (lane & 3) * 2 + r * 8;
    uint32_t out = 0;
#pragma unroll
    for (int s = 0; s < 2; ++s) {
        int ch = ch0 + s;
        int cin = mode0 ? (ch == 128 ? 0 : (ch < 128 ? ch + 1 : -1))
                        : (ch < CIN ? ch : -1);
        float w = 0.f;
        if (cin >= 0 && hid < HIDT)
            w = W[((size_t)(gate * HIDT + hid) * CIN + cin) * 9 + tap];
        out |= (uint32_t)f16bits(w) << (s * 16);
    }
    dst[idx] = out;
}

// Inject x_t at channel 128 of act0[t&1].
__global__ void inject_x(const float* __restrict__ hist, int t, uint16_t* __restrict__ act) {
    int idx = blockIdx.x * blockDim.x + threadIdx.x;
    if (idx >= NB * 4096) return;
    int b = idx >> 12, px = idx & 4095;
    float v = hist[((size_t)b * LT + t) * 4096 + px];
    size_t e = (((size_t)b * PADW + (px >> 6) + 1) * PADW + ((px & 63) + 1)) * CH + 128;
    act[e] = f16bits(v);
}

// ==================== fused ConvLSTM step: implicit GEMM on mma.sync fp16 ====================
// CTA: M=256 px (4 image rows), N=64 gate-interleaved oc'. 8 warps = 4(M) x 2(N), warp 64x32.
// 9 kc phases, DOUBLE-BUFFERED: fill(kc+1) overlaps compute(kc). Same 18 syncs as round 14.
// smem: 2 slots x (A 19008 + B 18432) = 74880 B.
__global__ void __launch_bounds__(256, 2)
step_mma(const uint16_t* __restrict__ act,
         const uint32_t* __restrict__ fragB, int ntiles,
         const float* __restrict__ bias, int HIDT,
         float* __restrict__ cstate,
         uint16_t* hdst_a, uint16_t* hdst_b, int ch_off,
         float* out_final) {
    extern __shared__ unsigned char smem[];
    const uint32_t sAsh = (uint32_t)__cvta_generic_to_shared(smem);

    const int tid = threadIdx.x, lane = tid & 31, warp = tid >> 5;
    const int warpM = warp & 3, warpN = warp >> 2;
    const int R4 = blockIdx.x * 4;           // image-row base
    const int b  = blockIdx.y;
    const int zt = blockIdx.z;
    const int nro = zt * 64;

    const int sw = (lane >> 2) & 1;
    const uint32_t laneOff0 = (uint32_t)lane * 32 + sw * 16;        // logical half 0 (i=0,1)
    const uint32_t laneOff1 = (uint32_t)lane * 32 + (1 - sw) * 16;  // logical half 1 (i=2,3)

    float acc[4][4][4];
#pragma unroll
    for (int m = 0; m < 4; ++m)
#pragma unroll
        for (int i = 0; i < 4; ++i)
#pragma unroll
            for (int k = 0; k < 4; ++k) acc[m][i][k] = 0.f;

    const size_t actbase = ((size_t)b * PADW + R4) * PADW * CH;

    // fill slot s with phase kc's A slab + B block, one cp.async group
    auto issue = [&](int kc, int s) {
        const uint32_t abuf = sAsh + (uint32_t)s * 37440u;
        for (int i = tid; i < 396 * 2; i += 256) {
            int rowid = i >> 1, half = i & 1;
            cpa16(abuf + rowid * 48 + half * 16,
                  act + actbase + (size_t)rowid * CH + kc * 16 + half * 8);
        }
        const uint4* src = (const uint4*)fragB + (size_t)(kc * ntiles + zt) * 1152;
        const uint32_t bbuf = abuf + 19008u;
        for (int i = tid; i < 1152; i += 256) cpa16(bbuf + i * 16, src + i);
        asm volatile("cp.async.commit_group;" ::: "memory");
    };

    issue(0, 0);
    for (int kc = 0; kc < 9; ++kc) {
        const int s = kc & 1;
        if (kc + 1 < 9) {
            issue(kc + 1, s ^ 1);     // slot s^1 free: compute(kc-1) ended with a sync
            asm volatile("cp.async.wait_group 1;" ::: "memory");
        } else {
            asm volatile("cp.async.wait_group 0;" ::: "memory");
        }
        __syncthreads();
        const uint32_t aBase = sAsh + (uint32_t)s * 37440u;
        const unsigned char* smB = smem + s * 37440 + 19008;
#pragma unroll
        for (int tap = 0; tap < 9; ++tap) {
            const int ky = tap / 3, kx = tap % 3;
            uint32_t a[4][4];
#pragma unroll
            for (int msub = 0; msub < 4; ++msub) {
                int m = warpM * 64 + msub * 16 + (lane & 15);
                int srow = ((m >> 6) + ky) * 66 + (m & 63) + kx;
                uint32_t ad = aBase + srow * 48 + (lane >> 4) * 16;
                asm volatile("ldmatrix.sync.aligned.m8n8.x4.shared.b16 {%0,%1,%2,%3}, [%4];"
                    : "=r"(a[msub][0]), "=r"(a[msub][1]), "=r"(a[msub][2]), "=r"(a[msub][3])
                    : "r"(ad));
            }
            const unsigned char* bblk = smB + (tap * 2 + warpN) * 1024;
            const uint4 vh0 = *(const uint4*)(bblk + laneOff0);   // i=0: x,y  i=1: z,w
            const uint4 vh1 = *(const uint4*)(bblk + laneOff1);   // i=2: x,y  i=3: z,w
            uint32_t bb[4][2] = {{vh0.x, vh0.y}, {vh0.z, vh0.w}, {vh1.x, vh1.y}, {vh1.z, vh1.w}};
#pragma unroll
            for (int i = 0; i < 4; ++i) {
#pragma unroll
                for (int msub = 0; msub < 4; ++msub) {
                    asm volatile(
                        "mma.sync.aligned.m16n8k16.row.col.f32.f16.f16.f32 "
                        "{%0,%1,%2,%3}, {%4,%5,%6,%7}, {%8,%9}, {%0,%1,%2,%3};"
                        : "+f"(acc[msub][i][0]), "+f"(acc[msub][i][1]),
                          "+f"(acc[msub][i][2]), "+f"(acc[msub][i][3])
                        : "r"(a[msub][0]), "r"(a[msub][1]), "r"(a[msub][2]), "r"(a[msub][3]),
                          "r"(bb[i][0]), "r"(bb[i][1]));
                }
            }
        }
        __syncthreads();     // compute(kc) done: slot s reusable at issue(kc+2)
    }

    // ---- epilogue: gather 4 gates per (px,hid) via shfl, LSTM update ----
    const int q = lane & 3;
    const bool evenq = !(q & 1);
#pragma unroll
    for (int msub = 0; msub < 4; ++msub) {
#pragma unroll
        for (int i = 0; i < 4; ++i) {
            float d0 = acc[msub][i][0], d1 = acc[msub][i][1];
            float d2 = acc[msub][i][2], d3 = acc[msub][i][3];
            float s0 = evenq ? d2 : d0;
            float s1 = evenq ? d3 : d1;
            float t0 = __shfl_xor_sync(0xffffffffu, s0, 1);
            float t1 = __shfl_xor_sync(0xffffffffu, s1, 1);
            float zi, zf, zo, zg;
            int pr;
            if (evenq) { zi = d0; zf = d1; zo = t0; zg = t1; pr = lane >> 2; }
            else       { zi = t0; zf = t1; zo = d2; zg = d3; pr = (lane >> 2) + 8; }
            const int m = warpM * 64 + msub * 16 + pr;
            const int hid = (nro >> 2) + warpN * 8 + i * 2 + (q >> 1);
            if (hid < HIDT) {
                zi += bias[hid];
                zf += bias[HIDT + hid];
                zo += bias[2 * HIDT + hid];
                zg += bias[3 * HIDT + hid];
                const int r_im = m >> 6, x = m & 63;
                const size_t cidx = ((size_t)b * 4096 + (R4 + r_im) * 64 + x) * HIDT + hid;
                float cp = cstate[cidx];
                float cn = fsig(zf) * cp + fsig(zi) * ftanh(zg);
                float hn = fsig(zo) * ftanh(cn);
                cstate[cidx] = cn;
                const uint16_t hf = f16bits(hn);
                const size_t e = (((size_t)b * PADW + R4 + r_im + 1) * PADW + x + 1) * CH + ch_off + hid;
                if (hdst_a) hdst_a[e] = hf;
                if (hdst_b) hdst_b[e] = hf;
                if (out_final)
                    out_final[((size_t)b * HIDT + hid) * 4096 + (R4 + r_im) * 64 + x] = hn;
            }
        }
    }
}

// ==================== host ====================
extern "C" void kernel_launch(void* const* d_in, const int* in_sizes, int n_in,
                              void* d_out, int out_size) {
    const float* hist = (const float*)d_in[0];
    const float* W0   = (const float*)d_in[2];
    const float* b0   = (const float*)d_in[3];
    const float* W1   = (const float*)d_in[4];
    const float* b1   = (const float*)d_in[5];
    float* out = (float*)d_out;

    uint16_t *a0p, *a1p;
    float *c0p, *c1p;
    uint32_t *fb0, *fb1;
    cudaGetSymbolAddress((void**)&a0p, g_act0);
    cudaGetSymbolAddress((void**)&a1p, g_act1);
    cudaGetSymbolAddress((void**)&c0p, g_c0);
    cudaGetSymbolAddress((void**)&c1p, g_c1);
    cudaGetSymbolAddress((void**)&fb0, g_fb0);
    cudaGetSymbolAddress((void**)&fb1, g_fb1);

    const int SMEM = 2 * (19008 + 18432);   // 74880
    cudaFuncSetAttribute(step_mma, cudaFuncAttributeMaxDynamicSharedMemorySize, SMEM);

    // deterministic replay: zero state + activations
    fill16<<<2048, 256>>>((uint4*)a0p, 2 * PLANE * 2 / 16);
    fill16<<<2048, 256>>>((uint4*)a1p, 2 * PLANE * 2 / 16);
    fill16<<<2048, 256>>>((uint4*)c0p, (size_t)NB * 4096 * 128 / 4);
    fill16<<<512,  256>>>((uint4*)c1p, (size_t)NB * 4096 * 12 / 4);

    const int tot0 = 9 * 8 * 9 * 2 * 32 * 8;
    const int tot1 = 9 * 1 * 9 * 2 * 32 * 8;
    prep_w<<<(tot0 + 255) / 256, 256>>>(W0, fb0, 128, 8, 129, 1, tot0);
    prep_w<<<(tot1 + 255) / 256, 256>>>(W1, fb1, 12, 1, 140, 0, tot1);

    for (int t = 0; t < LT; ++t) {
        uint16_t* act0_t = a0p + (size_t)(t & 1) * PLANE;
        uint16_t* act0_n = a0p + (size_t)((t + 1) & 1) * PLANE;
        uint16_t* act1_t = a1p + (size_t)(t & 1) * PLANE;
        uint16_t* act1_n = a1p + (size_t)((t + 1) & 1) * PLANE;

        inject_x<<<256, 256>>>(hist, t, act0_t);
        // L0: reads act0[t]; writes h0 -> act0[t+1] ch0..127 and act1[t] ch0..127
        step_mma<<<dim3(16, 16, 8), 256, SMEM>>>(
            act0_t, fb0, 8, b0, 128, c0p, act0_n, act1_t, 0, nullptr);
        // L1: reads act1[t]; writes h1 -> act1[t+1] ch128..139; last step -> out
        step_mma<<<dim3(16, 16, 1), 256, SMEM>>>(
            act1_t, fb1, 1, b1, 12, c1p,
            (t < LT - 1) ? act1_n : nullptr, nullptr, 128,
            (t == LT - 1) ? out : nullptr);
    }
}